// round 9
// baseline (speedup 1.0000x reference)
#include <cuda_runtime.h>
#include <cuda_bf16.h>
#include <cstdint>

#define DEVFN __device__ __forceinline__

// ---------------- problem sizes ----------------
#define MROWS 16384      // B*T = 8*2048
#define DIM   1024
#define HID   4096

// ---------------- scratch (device globals; no allocation) ----------------
__device__ __nv_bfloat16 g_qx1[(size_t)MROWS * DIM];   //  32 MB
__device__ __nv_bfloat16 g_qx2[(size_t)MROWS * HID];   // 128 MB
__device__ float         g_h  [(size_t)MROWS * HID];   // 256 MB (gelu output)
__device__ __nv_bfloat16 g_qw1[(size_t)HID * DIM];     //   8 MB
__device__ __nv_bfloat16 g_qw2[(size_t)DIM * HID];     //   8 MB
__device__ float g_sx1[MROWS];
__device__ float g_sx2[MROWS];
__device__ float g_part[2048];
__device__ float g_swinv[2];   // = max(mean|w|, EPS)  (i.e. 1/weight_scale)

// ---------------- small helpers ----------------
DEVFN float wsum(float v) {
#pragma unroll
    for (int o = 16; o > 0; o >>= 1) v += __shfl_xor_sync(0xffffffffu, v, o);
    return v;
}
DEVFN float wmaxr(float v) {
#pragma unroll
    for (int o = 16; o > 0; o >>= 1) v = fmaxf(v, __shfl_xor_sync(0xffffffffu, v, o));
    return v;
}
// deterministic block reductions (256 threads = 8 warps)
DEVFN float blockSum(float v, volatile float* sm) {
    int lane = threadIdx.x & 31, w = threadIdx.x >> 5;
    v = wsum(v);
    __syncthreads();
    if (lane == 0) sm[w] = v;
    __syncthreads();
    float r = sm[0];
#pragma unroll
    for (int i = 1; i < 8; i++) r += sm[i];
    return r;
}
DEVFN float blockMax(float v, volatile float* sm) {
    int lane = threadIdx.x & 31, w = threadIdx.x >> 5;
    v = wmaxr(v);
    __syncthreads();
    if (lane == 0) sm[w] = v;
    __syncthreads();
    float r = sm[0];
#pragma unroll
    for (int i = 1; i < 8; i++) r = fmaxf(r, sm[i]);
    return r;
}
DEVFN unsigned short bfbits(float f) {
    __nv_bfloat16 h = __float2bfloat16_rn(f);
    return *reinterpret_cast<unsigned short*>(&h);
}

// ---------------- weight quant: mean|w| (deterministic 2-stage) ----------------
__global__ __launch_bounds__(256) void absum_part(const float* __restrict__ w, int n,
                                                  float* __restrict__ part) {
    __shared__ float red[8];
    float s = 0.f;
    for (int i = blockIdx.x * 256 + threadIdx.x; i < n; i += gridDim.x * 256)
        s += fabsf(w[i]);
    s = blockSum(s, red);
    if (threadIdx.x == 0) part[blockIdx.x] = s;
}
__global__ __launch_bounds__(256) void absum_fin(const float* __restrict__ part, int np,
                                                 float n, int widx) {
    __shared__ float red[8];
    float s = 0.f;
    for (int i = threadIdx.x; i < np; i += 256) s += part[i];
    s = blockSum(s, red);
    if (threadIdx.x == 0) g_swinv[widx] = fmaxf(s / n, 1e-5f);
}
__global__ __launch_bounds__(256) void wquant(const float* __restrict__ w,
                                              __nv_bfloat16* __restrict__ q, int n4, int widx) {
    int i = blockIdx.x * 256 + threadIdx.x;
    if (i >= n4) return;
    float sc = 1.f / g_swinv[widx];
    float4 v = reinterpret_cast<const float4*>(w)[i];
    ushort4 o;
    o.x = bfbits(fminf(fmaxf(rintf(v.x * sc), -1.f), 1.f));
    o.y = bfbits(fminf(fmaxf(rintf(v.y * sc), -1.f), 1.f));
    o.z = bfbits(fminf(fmaxf(rintf(v.z * sc), -1.f), 1.f));
    o.w = bfbits(fminf(fmaxf(rintf(v.w * sc), -1.f), 1.f));
    reinterpret_cast<ushort4*>(q)[i] = o;
}

// ---------------- fused LayerNorm + act int8 fake-quant ----------------
template <int D>
__global__ __launch_bounds__(256) void ln_quant_kernel(
    const float* __restrict__ x, const float* __restrict__ lw, const float* __restrict__ lb,
    __nv_bfloat16* __restrict__ q, float* __restrict__ invsx) {
    constexpr int V4 = D / 1024;   // float4s per thread
    __shared__ float red[8];
    const size_t row = blockIdx.x;
    const int tid = threadIdx.x;
    const float4* xr = reinterpret_cast<const float4*>(x + row * D);
    float4 v[V4];
    float s = 0.f, s2 = 0.f;
#pragma unroll
    for (int i = 0; i < V4; i++) {
        v[i] = xr[tid + i * 256];
        s  += v[i].x + v[i].y + v[i].z + v[i].w;
        s2 += v[i].x * v[i].x + v[i].y * v[i].y + v[i].z * v[i].z + v[i].w * v[i].w;
    }
    s = blockSum(s, red);
    s2 = blockSum(s2, red);
    const float mu = s * (1.f / D);
    const float var = fmaxf(s2 * (1.f / D) - mu * mu, 0.f);
    const float rs = rsqrtf(var + 1e-5f);

    const float4* wr = reinterpret_cast<const float4*>(lw);
    const float4* br = reinterpret_cast<const float4*>(lb);
    float nv[V4 * 4];
    float amax = 0.f;
#pragma unroll
    for (int i = 0; i < V4; i++) {
        float4 wv = wr[tid + i * 256], bv = br[tid + i * 256];
        float a0 = (v[i].x - mu) * rs * wv.x + bv.x;
        float a1 = (v[i].y - mu) * rs * wv.y + bv.y;
        float a2 = (v[i].z - mu) * rs * wv.z + bv.z;
        float a3 = (v[i].w - mu) * rs * wv.w + bv.w;
        nv[i * 4 + 0] = a0; nv[i * 4 + 1] = a1; nv[i * 4 + 2] = a2; nv[i * 4 + 3] = a3;
        amax = fmaxf(amax, fmaxf(fmaxf(fabsf(a0), fabsf(a1)), fmaxf(fabsf(a2), fabsf(a3))));
    }
    amax = blockMax(amax, red);
    const float am = fmaxf(amax, 1e-5f);
    const float sc = 127.f / am;
    if (tid == 0) invsx[row] = am * (1.f / 127.f);
#pragma unroll
    for (int i = 0; i < V4; i++) {
        ushort4 o;
        o.x = bfbits(fminf(fmaxf(rintf(nv[i * 4 + 0] * sc), -128.f), 127.f));
        o.y = bfbits(fminf(fmaxf(rintf(nv[i * 4 + 1] * sc), -128.f), 127.f));
        o.z = bfbits(fminf(fmaxf(rintf(nv[i * 4 + 2] * sc), -128.f), 127.f));
        o.w = bfbits(fminf(fmaxf(rintf(nv[i * 4 + 3] * sc), -128.f), 127.f));
        reinterpret_cast<ushort4*>(q + row * D)[tid + i * 256] = o;
    }
}

// ---------------- bf16 HMMA GEMM (mma.sync, exact integer math) ----------------
#define BM 128
#define BN 128
#define BK 64                               // bf16: 64 elems = 128 bytes per smem row
#define NSTAGE 3
#define SMA_B (BM * 128)                    // 16 KB
#define SMB_B (BN * 128)                    // 16 KB
#define STAGE_B (SMA_B + SMB_B)             // 32 KB
#define GEMM_SMEM (NSTAGE * STAGE_B)        // 96 KB

DEVFN uint32_t s2u(const void* p) {
    uint32_t a;
    asm("{ .reg .u64 t; cvta.to.shared.u64 t, %1; cvt.u32.u64 %0, t; }" : "=r"(a) : "l"(p));
    return a;
}
DEVFN void cpa16(uint32_t s, const void* g) {
    asm volatile("cp.async.cg.shared.global [%0], [%1], 16;" :: "r"(s), "l"(g));
}
DEVFN void ldm_x4(uint32_t* r, uint32_t addr) {
    asm volatile("ldmatrix.sync.aligned.m8n8.x4.shared.b16 {%0,%1,%2,%3}, [%4];"
                 : "=r"(r[0]), "=r"(r[1]), "=r"(r[2]), "=r"(r[3]) : "r"(addr));
}
DEVFN void mma16816(float* d, const uint32_t* a, const uint32_t* b) {
    asm volatile(
        "mma.sync.aligned.m16n8k16.row.col.f32.bf16.bf16.f32 "
        "{%0,%1,%2,%3}, {%4,%5,%6,%7}, {%8,%9}, {%0,%1,%2,%3};"
        : "+f"(d[0]), "+f"(d[1]), "+f"(d[2]), "+f"(d[3])
        : "r"(a[0]), "r"(a[1]), "r"(a[2]), "r"(a[3]), "r"(b[0]), "r"(b[1]));
}

template <bool GELU>
__global__ __launch_bounds__(256, 2) void gemm_bl(
    const __nv_bfloat16* __restrict__ A,   // [M,K] qx (integer-valued bf16)
    const __nv_bfloat16* __restrict__ B,   // [N,K] qw (ternary bf16)
    const float* __restrict__ invsx,       // [M]
    const float* __restrict__ bias,        // [N]
    float* __restrict__ out,               // [M,N]
    int N, int K, int widx) {
    extern __shared__ char smem[];
    const uint32_t sb = s2u(smem);
    const int tid = threadIdx.x, lane = tid & 31, wid = tid >> 5;
    const int m0 = blockIdx.y * BM, n0 = blockIdx.x * BN;
    const int wm = (wid >> 1) * 32, wn = (wid & 1) * 64;   // warp tile 32x64
    const char* Ab = reinterpret_cast<const char*>(A) + (size_t)m0 * K * 2;
    const char* Bb = reinterpret_cast<const char*>(B) + (size_t)n0 * K * 2;
    const size_t rowK = (size_t)K * 2;
    const int nch = K / BK;

    // stage loader: A 128 rows + B 128 rows, each 128 bytes, SW swizzle
    auto loadStage = [&](int stg, int c) {
        const uint32_t da = sb + stg * STAGE_B;
        const uint32_t db = da + SMA_B;
        const char* As = Ab + (size_t)c * BK * 2;
        const char* Bs = Bb + (size_t)c * BK * 2;
#pragma unroll
        for (int i = 0; i < 4; i++) {
            int idx = tid + i * 256;
            int row = idx >> 3, seg = idx & 7;
            uint32_t so = row * 128 + ((seg * 16) ^ ((row & 7) << 4));
            size_t go = (size_t)row * rowK + seg * 16;
            cpa16(da + so, As + go);
            cpa16(db + so, Bs + go);
        }
        asm volatile("cp.async.commit_group;" ::: "memory");
    };

    loadStage(0, 0);
    if (nch > 1) loadStage(1, 1);

    float acc[2][8][4];
#pragma unroll
    for (int i = 0; i < 2; i++)
#pragma unroll
        for (int j = 0; j < 8; j++)
#pragma unroll
            for (int t = 0; t < 4; t++) acc[i][j][t] = 0.f;

    // per-lane ldmatrix row indices (fixed per thread)
    const int arow_in = lane & 15;                              // A: m within 16-block
    const int ahalf   = (lane >> 4) << 4;                       // A: k half byte-offset
    const int brow_in = ((lane >> 4) << 3) + (lane & 7);        // B: n within 16-block
    const int bhalf   = ((lane >> 3) & 1) << 4;                 // B: k half byte-offset

    for (int c = 0; c < nch; c++) {
        const int st = c % NSTAGE;
        // ensure chunk c's group is complete: if a later group exists, allow it
        if (c + 1 < nch) asm volatile("cp.async.wait_group 1;" ::: "memory");
        else             asm volatile("cp.async.wait_group 0;" ::: "memory");
        __syncthreads();
        if (c + 2 < nch) loadStage((c + 2) % NSTAGE, c + 2);
        const uint32_t sa = sb + st * STAGE_B;
        const uint32_t sB = sa + SMA_B;
#pragma unroll
        for (int ks = 0; ks < BK / 16; ks++) {
            uint32_t af[2][4], bf[4][4];
            const int kba = ks * 32 + ahalf;
#pragma unroll
            for (int mi = 0; mi < 2; mi++) {
                int row = wm + mi * 16 + arow_in;
                ldm_x4(af[mi], sa + row * 128 + (kba ^ ((row & 7) << 4)));
            }
            const int kbb = ks * 32 + bhalf;
#pragma unroll
            for (int nb = 0; nb < 4; nb++) {
                int row = wn + nb * 16 + brow_in;
                ldm_x4(bf[nb], sB + row * 128 + (kbb ^ ((row & 7) << 4)));
            }
#pragma unroll
            for (int mi = 0; mi < 2; mi++)
#pragma unroll
                for (int nb = 0; nb < 4; nb++) {
                    mma16816(acc[mi][nb * 2 + 0], af[mi], &bf[nb][0]);
                    mma16816(acc[mi][nb * 2 + 1], af[mi], &bf[nb][2]);
                }
        }
    }

    // epilogue: scale + bias (+ exact GELU), direct global stores
    const float swv = g_swinv[widx];
    const int mr = m0 + wm + (lane >> 2);
    float isx[4];
    isx[0] = invsx[mr] * swv;
    isx[1] = invsx[mr + 8] * swv;
    isx[2] = invsx[mr + 16] * swv;
    isx[3] = invsx[mr + 24] * swv;
#pragma unroll
    for (int mi = 0; mi < 2; mi++) {
#pragma unroll
        for (int nb = 0; nb < 8; nb++) {
            const int col = n0 + wn + nb * 8 + 2 * (lane & 3);
            const float b0 = bias[col], b1 = bias[col + 1];
            float v0 = acc[mi][nb][0] * isx[mi * 2 + 0] + b0;
            float v1 = acc[mi][nb][1] * isx[mi * 2 + 0] + b1;
            float v2 = acc[mi][nb][2] * isx[mi * 2 + 1] + b0;
            float v3 = acc[mi][nb][3] * isx[mi * 2 + 1] + b1;
            if (GELU) {
                v0 = 0.5f * v0 * (1.f + erff(v0 * 0.70710678118654752f));
                v1 = 0.5f * v1 * (1.f + erff(v1 * 0.70710678118654752f));
                v2 = 0.5f * v2 * (1.f + erff(v2 * 0.70710678118654752f));
                v3 = 0.5f * v3 * (1.f + erff(v3 * 0.70710678118654752f));
            }
            const int r0 = mr + mi * 16;
            *reinterpret_cast<float2*>(out + (size_t)r0 * N + col) = make_float2(v0, v1);
            *reinterpret_cast<float2*>(out + (size_t)(r0 + 8) * N + col) = make_float2(v2, v3);
        }
    }
}

// ---------------- launch ----------------
extern "C" void kernel_launch(void* const* d_in, const int* in_sizes, int n_in,
                              void* d_out, int out_size) {
    (void)in_sizes; (void)n_in; (void)out_size;
    const float* x    = (const float*)d_in[0];
    const float* ln1w = (const float*)d_in[1];
    const float* ln1b = (const float*)d_in[2];
    const float* w1   = (const float*)d_in[3];
    const float* b1   = (const float*)d_in[4];
    const float* ln2w = (const float*)d_in[5];
    const float* ln2b = (const float*)d_in[6];
    const float* w2   = (const float*)d_in[7];
    const float* b2   = (const float*)d_in[8];
    float* out = (float*)d_out;

    void *p_qx1, *p_qx2, *p_h, *p_qw1, *p_qw2, *p_sx1, *p_sx2, *p_part;
    cudaGetSymbolAddress(&p_qx1, g_qx1);
    cudaGetSymbolAddress(&p_qx2, g_qx2);
    cudaGetSymbolAddress(&p_h, g_h);
    cudaGetSymbolAddress(&p_qw1, g_qw1);
    cudaGetSymbolAddress(&p_qw2, g_qw2);
    cudaGetSymbolAddress(&p_sx1, g_sx1);
    cudaGetSymbolAddress(&p_sx2, g_sx2);
    cudaGetSymbolAddress(&p_part, g_part);

    cudaFuncSetAttribute((const void*)gemm_bl<true>,
                         cudaFuncAttributeMaxDynamicSharedMemorySize, GEMM_SMEM);
    cudaFuncSetAttribute((const void*)gemm_bl<false>,
                         cudaFuncAttributeMaxDynamicSharedMemorySize, GEMM_SMEM);

    const int n1 = HID * DIM, n2 = DIM * HID;

    // weight 1: mean|w| -> ternary bf16
    absum_part<<<1024, 256>>>(w1, n1, (float*)p_part);
    absum_fin<<<1, 256>>>((const float*)p_part, 1024, (float)n1, 0);
    wquant<<<(n1 / 4 + 255) / 256, 256>>>(w1, (__nv_bfloat16*)p_qw1, n1 / 4, 0);
    // weight 2
    absum_part<<<1024, 256>>>(w2, n2, (float*)p_part);
    absum_fin<<<1, 256>>>((const float*)p_part, 1024, (float)n2, 1);
    wquant<<<(n2 / 4 + 255) / 256, 256>>>(w2, (__nv_bfloat16*)p_qw2, n2 / 4, 1);

    // LN1 + act quant
    ln_quant_kernel<DIM><<<MROWS, 256>>>(x, ln1w, ln1b,
                                         (__nv_bfloat16*)p_qx1, (float*)p_sx1);
    // GEMM1 + bias + exact GELU -> g_h
    {
        dim3 g(HID / BN, MROWS / BM);
        gemm_bl<true><<<g, 256, GEMM_SMEM>>>((const __nv_bfloat16*)p_qx1,
                                             (const __nv_bfloat16*)p_qw1,
                                             (const float*)p_sx1, b1, (float*)p_h,
                                             HID, DIM, 0);
    }
    // LN2 + act quant
    ln_quant_kernel<HID><<<MROWS, 256>>>((const float*)p_h, ln2w, ln2b,
                                         (__nv_bfloat16*)p_qx2, (float*)p_sx2);
    // GEMM2 + bias -> out
    {
        dim3 g(DIM / BN, MROWS / BM);
        gemm_bl<false><<<g, 256, GEMM_SMEM>>>((const __nv_bfloat16*)p_qx2,
                                              (const __nv_bfloat16*)p_qw2,
                                              (const float*)p_sx2, b2, out,
                                              DIM, HID, 1);
    }
}

// round 11
// speedup vs baseline: 1.5576x; 1.5576x over previous
#include <cuda_runtime.h>
#include <cuda_bf16.h>
#include <cstdint>

#define DEVFN __device__ __forceinline__

// ---------------- problem sizes ----------------
#define MROWS 16384      // B*T = 8*2048
#define DIM   1024
#define HID   4096

// ---------------- scratch (device globals; no allocation) ----------------
__device__ __nv_bfloat16 g_qx1[(size_t)MROWS * DIM];   //  32 MB
__device__ __nv_bfloat16 g_qx2[(size_t)MROWS * HID];   // 128 MB
__device__ float         g_h  [(size_t)MROWS * HID];   // 256 MB (gelu output)
__device__ __nv_bfloat16 g_qw1[(size_t)HID * DIM];     //   8 MB
__device__ __nv_bfloat16 g_qw2[(size_t)DIM * HID];     //   8 MB
__device__ float g_sx1[MROWS];
__device__ float g_sx2[MROWS];
__device__ float g_part[2048];
__device__ float g_swinv[2];   // = max(mean|w|, EPS)  (i.e. 1/weight_scale)

// ---------------- small helpers ----------------
DEVFN float wsum(float v) {
#pragma unroll
    for (int o = 16; o > 0; o >>= 1) v += __shfl_xor_sync(0xffffffffu, v, o);
    return v;
}
DEVFN float wmaxr(float v) {
#pragma unroll
    for (int o = 16; o > 0; o >>= 1) v = fmaxf(v, __shfl_xor_sync(0xffffffffu, v, o));
    return v;
}
// deterministic block reductions (256 threads = 8 warps)
DEVFN float blockSum(float v, volatile float* sm) {
    int lane = threadIdx.x & 31, w = threadIdx.x >> 5;
    v = wsum(v);
    __syncthreads();
    if (lane == 0) sm[w] = v;
    __syncthreads();
    float r = sm[0];
#pragma unroll
    for (int i = 1; i < 8; i++) r += sm[i];
    return r;
}
DEVFN float blockMax(float v, volatile float* sm) {
    int lane = threadIdx.x & 31, w = threadIdx.x >> 5;
    v = wmaxr(v);
    __syncthreads();
    if (lane == 0) sm[w] = v;
    __syncthreads();
    float r = sm[0];
#pragma unroll
    for (int i = 1; i < 8; i++) r = fmaxf(r, sm[i]);
    return r;
}
DEVFN unsigned short bfbits(float f) {
    __nv_bfloat16 h = __float2bfloat16_rn(f);
    return *reinterpret_cast<unsigned short*>(&h);
}

// ---------------- weight quant: mean|w| (deterministic 2-stage) ----------------
__global__ __launch_bounds__(256) void absum_part(const float* __restrict__ w, int n4,
                                                  float* __restrict__ part) {
    __shared__ float red[8];
    const float4* w4 = reinterpret_cast<const float4*>(w);
    float s = 0.f;
    for (int i = blockIdx.x * 256 + threadIdx.x; i < n4; i += gridDim.x * 256) {
        float4 v = w4[i];
        s += fabsf(v.x) + fabsf(v.y) + fabsf(v.z) + fabsf(v.w);
    }
    s = blockSum(s, red);
    if (threadIdx.x == 0) part[blockIdx.x] = s;
}
__global__ __launch_bounds__(256) void absum_fin(const float* __restrict__ part, int np,
                                                 float n, int widx) {
    __shared__ float red[8];
    float s = 0.f;
    for (int i = threadIdx.x; i < np; i += 256) s += part[i];
    s = blockSum(s, red);
    if (threadIdx.x == 0) g_swinv[widx] = fmaxf(s / n, 1e-5f);
}
__global__ __launch_bounds__(256) void wquant(const float* __restrict__ w,
                                              __nv_bfloat16* __restrict__ q, int n4, int widx) {
    int i = blockIdx.x * 256 + threadIdx.x;
    if (i >= n4) return;
    float sc = 1.f / g_swinv[widx];
    float4 v = reinterpret_cast<const float4*>(w)[i];
    ushort4 o;
    o.x = bfbits(fminf(fmaxf(rintf(v.x * sc), -1.f), 1.f));
    o.y = bfbits(fminf(fmaxf(rintf(v.y * sc), -1.f), 1.f));
    o.z = bfbits(fminf(fmaxf(rintf(v.z * sc), -1.f), 1.f));
    o.w = bfbits(fminf(fmaxf(rintf(v.w * sc), -1.f), 1.f));
    reinterpret_cast<ushort4*>(q)[i] = o;
}

// ---------------- fused LayerNorm + act int8 fake-quant ----------------
template <int D>
__global__ __launch_bounds__(256) void ln_quant_kernel(
    const float* __restrict__ x, const float* __restrict__ lw, const float* __restrict__ lb,
    __nv_bfloat16* __restrict__ q, float* __restrict__ invsx) {
    constexpr int V4 = D / 1024;   // float4s per thread
    __shared__ float red[8];
    const size_t row = blockIdx.x;
    const int tid = threadIdx.x;
    const float4* xr = reinterpret_cast<const float4*>(x + row * D);
    float4 v[V4];
    float s = 0.f, s2 = 0.f;
#pragma unroll
    for (int i = 0; i < V4; i++) {
        v[i] = xr[tid + i * 256];
        s  += v[i].x + v[i].y + v[i].z + v[i].w;
        s2 += v[i].x * v[i].x + v[i].y * v[i].y + v[i].z * v[i].z + v[i].w * v[i].w;
    }
    s = blockSum(s, red);
    s2 = blockSum(s2, red);
    const float mu = s * (1.f / D);
    const float var = fmaxf(s2 * (1.f / D) - mu * mu, 0.f);
    const float rs = rsqrtf(var + 1e-5f);

    const float4* wr = reinterpret_cast<const float4*>(lw);
    const float4* br = reinterpret_cast<const float4*>(lb);
    float nv[V4 * 4];
    float amax = 0.f;
#pragma unroll
    for (int i = 0; i < V4; i++) {
        float4 wv = wr[tid + i * 256], bv = br[tid + i * 256];
        float a0 = (v[i].x - mu) * rs * wv.x + bv.x;
        float a1 = (v[i].y - mu) * rs * wv.y + bv.y;
        float a2 = (v[i].z - mu) * rs * wv.z + bv.z;
        float a3 = (v[i].w - mu) * rs * wv.w + bv.w;
        nv[i * 4 + 0] = a0; nv[i * 4 + 1] = a1; nv[i * 4 + 2] = a2; nv[i * 4 + 3] = a3;
        amax = fmaxf(amax, fmaxf(fmaxf(fabsf(a0), fabsf(a1)), fmaxf(fabsf(a2), fabsf(a3))));
    }
    amax = blockMax(amax, red);
    const float am = fmaxf(amax, 1e-5f);
    const float sc = 127.f / am;
    if (tid == 0) invsx[row] = am * (1.f / 127.f);
#pragma unroll
    for (int i = 0; i < V4; i++) {
        ushort4 o;
        o.x = bfbits(fminf(fmaxf(rintf(nv[i * 4 + 0] * sc), -128.f), 127.f));
        o.y = bfbits(fminf(fmaxf(rintf(nv[i * 4 + 1] * sc), -128.f), 127.f));
        o.z = bfbits(fminf(fmaxf(rintf(nv[i * 4 + 2] * sc), -128.f), 127.f));
        o.w = bfbits(fminf(fmaxf(rintf(nv[i * 4 + 3] * sc), -128.f), 127.f));
        reinterpret_cast<ushort4*>(q + row * D)[tid + i * 256] = o;
    }
}

// ---------------- bf16 HMMA GEMM (mma.sync, exact integer math) — R6 config ----------------
#define BM 128
#define BN 128
#define BK 64
#define STAGE_T (128 * 128)                 // 16 KB per tile stage (128 rows x 128B)
#define SMA_OFF 0
#define SMB_OFF (2 * STAGE_T)
#define GEMM_SMEM (4 * STAGE_T)             // 64 KB

DEVFN uint32_t s2u(const void* p) {
    uint32_t a;
    asm("{ .reg .u64 t; cvta.to.shared.u64 t, %1; cvt.u32.u64 %0, t; }" : "=r"(a) : "l"(p));
    return a;
}
DEVFN void cpa16(uint32_t s, const void* g) {
    asm volatile("cp.async.cg.shared.global [%0], [%1], 16;" :: "r"(s), "l"(g));
}
DEVFN void ldm_x4(uint32_t* r, uint32_t addr) {
    asm volatile("ldmatrix.sync.aligned.m8n8.x4.shared.b16 {%0,%1,%2,%3}, [%4];"
                 : "=r"(r[0]), "=r"(r[1]), "=r"(r[2]), "=r"(r[3]) : "r"(addr));
}
DEVFN void mma16816(float* d, const uint32_t* a, const uint32_t* b) {
    asm volatile(
        "mma.sync.aligned.m16n8k16.row.col.f32.bf16.bf16.f32 "
        "{%0,%1,%2,%3}, {%4,%5,%6,%7}, {%8,%9}, {%0,%1,%2,%3};"
        : "+f"(d[0]), "+f"(d[1]), "+f"(d[2]), "+f"(d[3])
        : "r"(a[0]), "r"(a[1]), "r"(a[2]), "r"(a[3]), "r"(b[0]), "r"(b[1]));
}

template <bool GELU>
__global__ __launch_bounds__(256) void gemm_bl(
    const __nv_bfloat16* __restrict__ A,   // [M,K] qx (integer-valued bf16)
    const __nv_bfloat16* __restrict__ B,   // [N,K] qw (ternary bf16)
    const float* __restrict__ invsx,       // [M]
    const float* __restrict__ bias,        // [N]
    float* __restrict__ out,               // [M,N]
    int N, int K, int widx) {
    extern __shared__ char smem[];
    const uint32_t sb = s2u(smem);
    const int tid = threadIdx.x, lane = tid & 31, wid = tid >> 5;
    const int m0 = blockIdx.y * BM, n0 = blockIdx.x * BN;
    const int wm = (wid >> 1) * 32, wn = (wid & 1) * 64;   // warp tile 32x64
    const char* Ab = reinterpret_cast<const char*>(A) + (size_t)m0 * K * 2;
    const char* Bb = reinterpret_cast<const char*>(B) + (size_t)n0 * K * 2;
    const size_t rowK = (size_t)K * 2;
    const int nch = K / BK;

    // tile loader: 128 rows x 128 bytes, SW128 swizzle ((row&7)<<4 on 16B column)
    auto loadT = [&](uint32_t dst, const char* src) {
#pragma unroll
        for (int i = 0; i < 4; i++) {
            int idx = tid + i * 256;
            int row = idx >> 3, seg = idx & 7;
            cpa16(dst + row * 128 + ((seg * 16) ^ ((row & 7) << 4)),
                  src + (size_t)row * rowK + seg * 16);
        }
    };

    // prologue: chunk 0 -> stage 0
    loadT(sb + SMA_OFF, Ab);
    loadT(sb + SMB_OFF, Bb);
    asm volatile("cp.async.commit_group;" ::: "memory");

    float acc[2][8][4];
#pragma unroll
    for (int i = 0; i < 2; i++)
#pragma unroll
        for (int j = 0; j < 8; j++)
#pragma unroll
            for (int t = 0; t < 4; t++) acc[i][j][t] = 0.f;

    // per-lane ldmatrix row indices (fixed per thread)
    const int arow_in = lane & 15;                              // A: m within 16-block
    const int ahalf   = (lane >> 4) << 4;                       // A: k half byte-offset
    const int brow_in = ((lane >> 4) << 3) + (lane & 7);        // B: n within 16-block
    const int bhalf   = ((lane >> 3) & 1) << 4;                 // B: k half byte-offset

    for (int c = 0; c < nch; c++) {
        const int st = c & 1;
        asm volatile("cp.async.wait_group 0;" ::: "memory");
        __syncthreads();
        if (c + 1 < nch) {
            loadT(sb + SMA_OFF + (st ^ 1) * STAGE_T, Ab + (size_t)(c + 1) * BK * 2);
            loadT(sb + SMB_OFF + (st ^ 1) * STAGE_T, Bb + (size_t)(c + 1) * BK * 2);
            asm volatile("cp.async.commit_group;" ::: "memory");
        }
        const uint32_t sa = sb + SMA_OFF + st * STAGE_T;
        const uint32_t sB = sb + SMB_OFF + st * STAGE_T;
#pragma unroll
        for (int ks = 0; ks < BK / 16; ks++) {
            uint32_t af[2][4], bf[4][4];
            const int kba = ks * 32 + ahalf;
#pragma unroll
            for (int mi = 0; mi < 2; mi++) {
                int row = wm + mi * 16 + arow_in;
                ldm_x4(af[mi], sa + row * 128 + (kba ^ ((row & 7) << 4)));
            }
            const int kbb = ks * 32 + bhalf;
#pragma unroll
            for (int nb = 0; nb < 4; nb++) {
                int row = wn + nb * 16 + brow_in;
                ldm_x4(bf[nb], sB + row * 128 + (kbb ^ ((row & 7) << 4)));
            }
#pragma unroll
            for (int mi = 0; mi < 2; mi++)
#pragma unroll
                for (int nb = 0; nb < 4; nb++) {
                    mma16816(acc[mi][nb * 2 + 0], af[mi], &bf[nb][0]);
                    mma16816(acc[mi][nb * 2 + 1], af[mi], &bf[nb][2]);
                }
        }
    }

    // epilogue: scale + bias (+ exact GELU), direct global stores
    const float swv = g_swinv[widx];
    const int mr = m0 + wm + (lane >> 2);
    float isx[4];
    isx[0] = invsx[mr] * swv;
    isx[1] = invsx[mr + 8] * swv;
    isx[2] = invsx[mr + 16] * swv;
    isx[3] = invsx[mr + 24] * swv;
#pragma unroll
    for (int mi = 0; mi < 2; mi++) {
#pragma unroll
        for (int nb = 0; nb < 8; nb++) {
            const int col = n0 + wn + nb * 8 + 2 * (lane & 3);
            const float b0 = bias[col], b1 = bias[col + 1];
            float v0 = acc[mi][nb][0] * isx[mi * 2 + 0] + b0;
            float v1 = acc[mi][nb][1] * isx[mi * 2 + 0] + b1;
            float v2 = acc[mi][nb][2] * isx[mi * 2 + 1] + b0;
            float v3 = acc[mi][nb][3] * isx[mi * 2 + 1] + b1;
            if (GELU) {
                v0 = 0.5f * v0 * (1.f + erff(v0 * 0.70710678118654752f));
                v1 = 0.5f * v1 * (1.f + erff(v1 * 0.70710678118654752f));
                v2 = 0.5f * v2 * (1.f + erff(v2 * 0.70710678118654752f));
                v3 = 0.5f * v3 * (1.f + erff(v3 * 0.70710678118654752f));
            }
            const int r0 = mr + mi * 16;
            *reinterpret_cast<float2*>(out + (size_t)r0 * N + col) = make_float2(v0, v1);
            *reinterpret_cast<float2*>(out + (size_t)(r0 + 8) * N + col) = make_float2(v2, v3);
        }
    }
}

// ---------------- launch ----------------
// Order chosen so gemm_bl<true> is the 6th kernel launch (ncu -s 5 -c 1 captures it).
extern "C" void kernel_launch(void* const* d_in, const int* in_sizes, int n_in,
                              void* d_out, int out_size) {
    (void)in_sizes; (void)n_in; (void)out_size;
    const float* x    = (const float*)d_in[0];
    const float* ln1w = (const float*)d_in[1];
    const float* ln1b = (const float*)d_in[2];
    const float* w1   = (const float*)d_in[3];
    const float* b1   = (const float*)d_in[4];
    const float* ln2w = (const float*)d_in[5];
    const float* ln2b = (const float*)d_in[6];
    const float* w2   = (const float*)d_in[7];
    const float* b2   = (const float*)d_in[8];
    float* out = (float*)d_out;

    void *p_qx1, *p_qx2, *p_h, *p_qw1, *p_qw2, *p_sx1, *p_sx2, *p_part;
    cudaGetSymbolAddress(&p_qx1, g_qx1);
    cudaGetSymbolAddress(&p_qx2, g_qx2);
    cudaGetSymbolAddress(&p_h, g_h);
    cudaGetSymbolAddress(&p_qw1, g_qw1);
    cudaGetSymbolAddress(&p_qw2, g_qw2);
    cudaGetSymbolAddress(&p_sx1, g_sx1);
    cudaGetSymbolAddress(&p_sx2, g_sx2);
    cudaGetSymbolAddress(&p_part, g_part);

    cudaFuncSetAttribute((const void*)gemm_bl<true>,
                         cudaFuncAttributeMaxDynamicSharedMemorySize, GEMM_SMEM);
    cudaFuncSetAttribute((const void*)gemm_bl<false>,
                         cudaFuncAttributeMaxDynamicSharedMemorySize, GEMM_SMEM);

    const int n1 = HID * DIM, n2 = DIM * HID;

    // 1-3: weight 1 chain -> qw1
    absum_part<<<1024, 256>>>(w1, n1 / 4, (float*)p_part);
    absum_fin<<<1, 256>>>((const float*)p_part, 1024, (float)n1, 0);
    wquant<<<(n1 / 4 + 255) / 256, 256>>>(w1, (__nv_bfloat16*)p_qw1, n1 / 4, 0);
    // 4: LN1 + act quant -> qx1
    ln_quant_kernel<DIM><<<MROWS, 256>>>(x, ln1w, ln1b,
                                         (__nv_bfloat16*)p_qx1, (float*)p_sx1);
    // 5: weight 2 partial sums (independent)
    absum_part<<<1024, 256>>>(w2, n2 / 4, (float*)p_part);
    // 6: GEMM1 + bias + exact GELU -> g_h   (profiled launch)
    {
        dim3 g(HID / BN, MROWS / BM);
        gemm_bl<true><<<g, 256, GEMM_SMEM>>>((const __nv_bfloat16*)p_qx1,
                                             (const __nv_bfloat16*)p_qw1,
                                             (const float*)p_sx1, b1, (float*)p_h,
                                             HID, DIM, 0);
    }
    // 7-8: weight 2 chain -> qw2
    absum_fin<<<1, 256>>>((const float*)p_part, 1024, (float)n2, 1);
    wquant<<<(n2 / 4 + 255) / 256, 256>>>(w2, (__nv_bfloat16*)p_qw2, n2 / 4, 1);
    // 9: LN2 + act quant -> qx2
    ln_quant_kernel<HID><<<MROWS, 256>>>((const float*)p_h, ln2w, ln2b,
                                         (__nv_bfloat16*)p_qx2, (float*)p_sx2);
    // 10: GEMM2 + bias -> out
    {
        dim3 g(DIM / BN, MROWS / BM);
        gemm_bl<false><<<g, 256, GEMM_SMEM>>>((const __nv_bfloat16*)p_qx2,
                                              (const __nv_bfloat16*)p_qw2,
                                              (const float*)p_sx2, b2, out,
                                              DIM, HID, 1);
    }
}